// round 1
// baseline (speedup 1.0000x reference)
#include <cuda_runtime.h>

#define NROW 8192
#define DIM 512
#define KSEL 49
#define TILE 128
#define KT 16
#define NTILE (NROW/TILE)   /* 64 */
#define SPAD 132

// ---------------- scratch (static device globals; no allocation) ----------------
__device__ float g_Wc[DIM*DIM];
__device__ float g_bc[DIM];
__device__ float g_E[(size_t)NROW*DIM];
__device__ float g_C[(size_t)NROW*NROW];

// ---------------- packed f32x2 helpers (Blackwell FFMA2 path) ----------------
__device__ __forceinline__ unsigned long long ffma2(unsigned long long a,
                                                    unsigned long long b,
                                                    unsigned long long c) {
    unsigned long long d;
    asm("fma.rn.f32x2 %0, %1, %2, %3;" : "=l"(d) : "l"(a), "l"(b), "l"(c));
    return d;
}
__device__ __forceinline__ unsigned long long dup2(float x) {
    unsigned long long r; unsigned int u = __float_as_uint(x);
    asm("mov.b64 %0, {%1, %1};" : "=l"(r) : "r"(u));
    return r;
}
__device__ __forceinline__ unsigned long long pk2(float x, float y) {
    unsigned long long r;
    unsigned int ux = __float_as_uint(x), uy = __float_as_uint(y);
    asm("mov.b64 %0, {%1, %2};" : "=l"(r) : "r"(ux), "r"(uy));
    return r;
}
__device__ __forceinline__ float2 unpk(unsigned long long v) {
    unsigned int lo, hi;
    asm("mov.b64 {%0, %1}, %2;" : "=r"(lo), "=r"(hi) : "l"(v));
    float2 f; f.x = __uint_as_float(lo); f.y = __uint_as_float(hi);
    return f;
}

// ---------------- orderable float<->uint keys for radix select ----------------
__device__ __forceinline__ unsigned int enc_key(float f) {
    unsigned int u = __float_as_uint(f);
    return (u & 0x80000000u) ? ~u : (u | 0x80000000u);
}
__device__ __forceinline__ float dec_key(unsigned int k) {
    return (k & 0x80000000u) ? __uint_as_float(k & 0x7fffffffu)
                             : __uint_as_float(~k);
}

// ---------------- kernel 1: softmax(weights) + combine 4 projections ----------------
__global__ void k_combine(const float* __restrict__ sw,
    const float* __restrict__ W0, const float* __restrict__ W1,
    const float* __restrict__ W2, const float* __restrict__ W3,
    const float* __restrict__ b0, const float* __restrict__ b1,
    const float* __restrict__ b2, const float* __restrict__ b3)
{
    float a0 = sw[0], a1 = sw[1], a2 = sw[2], a3 = sw[3];
    float m  = fmaxf(fmaxf(a0, a1), fmaxf(a2, a3));
    float e0 = expf(a0 - m), e1 = expf(a1 - m), e2 = expf(a2 - m), e3 = expf(a3 - m);
    float inv = 1.0f / (e0 + e1 + e2 + e3);
    float w0 = e0 * inv, w1 = e1 * inv, w2 = e2 * inv, w3 = e3 * inv;
    int i = blockIdx.x * blockDim.x + threadIdx.x;
    if (i < DIM * DIM)
        g_Wc[i] = w0 * W0[i] + w1 * W1[i] + w2 * W2[i] + w3 * W3[i];
    if (i < DIM)
        g_bc[i] = w0 * b0[i] + w1 * b1[i] + w2 * b2[i] + w3 * b3[i];
}

// ---------------- shared NT-GEMM core: C[r,c] = sum_k A[r,k]*B[c,k] ----------------
// 128x128 tile, 256 threads, 8x8 microtile, KT=16, double-buffered smem,
// packed f32x2 FMA. Column microtile split as {tx*4..+3} and {64+tx*4..+3}
// so smem b-loads resolve in 2 phases.
template<int KDIM>
__device__ __forceinline__ void gemm_core(const float* __restrict__ A,
                                          const float* __restrict__ B,
                                          int rowBase, int colBase,
                                          int lda, int ldb,
                                          unsigned long long (&acc)[8][4])
{
    __shared__ float As[2][KT][SPAD];
    __shared__ float Bs[2][KT][SPAD];
    const int tid = threadIdx.x;
    const int tx = tid & 15, ty = tid >> 4;
    const int ri0 = ty * 8;
    const int c0  = tx * 4;
    float4 ra[2], rb[2];

    #pragma unroll
    for (int i = 0; i < 8; i++)
        #pragma unroll
        for (int j = 0; j < 4; j++) acc[i][j] = 0ull;

    auto loadG = [&](int k0) {
        #pragma unroll
        for (int l = 0; l < 2; l++) {
            int li = tid * 2 + l;
            int row = li >> 2, q = li & 3;
            ra[l] = *(const float4*)(A + (size_t)(rowBase + row) * lda + k0 + q * 4);
            rb[l] = *(const float4*)(B + (size_t)(colBase + row) * ldb + k0 + q * 4);
        }
    };
    auto storeS = [&](int buf) {
        #pragma unroll
        for (int l = 0; l < 2; l++) {
            int li = tid * 2 + l;
            int row = li >> 2, q = li & 3;
            As[buf][q*4+0][row] = ra[l].x; As[buf][q*4+1][row] = ra[l].y;
            As[buf][q*4+2][row] = ra[l].z; As[buf][q*4+3][row] = ra[l].w;
            Bs[buf][q*4+0][row] = rb[l].x; Bs[buf][q*4+1][row] = rb[l].y;
            Bs[buf][q*4+2][row] = rb[l].z; Bs[buf][q*4+3][row] = rb[l].w;
        }
    };

    loadG(0);
    storeS(0);
    __syncthreads();

    const int nk = KDIM / KT;
    for (int t = 0; t < nk; t++) {
        int buf = t & 1;
        if (t + 1 < nk) loadG((t + 1) * KT);
        #pragma unroll
        for (int kk = 0; kk < KT; kk++) {
            float4 a0 = *(const float4*)&As[buf][kk][ri0];
            float4 a1 = *(const float4*)&As[buf][kk][ri0 + 4];
            float4 b0 = *(const float4*)&Bs[buf][kk][c0];
            float4 b1 = *(const float4*)&Bs[buf][kk][64 + c0];
            unsigned long long bp[4];
            bp[0] = pk2(b0.x, b0.y); bp[1] = pk2(b0.z, b0.w);
            bp[2] = pk2(b1.x, b1.y); bp[3] = pk2(b1.z, b1.w);
            float av[8] = {a0.x, a0.y, a0.z, a0.w, a1.x, a1.y, a1.z, a1.w};
            #pragma unroll
            for (int i = 0; i < 8; i++) {
                unsigned long long ad = dup2(av[i]);
                #pragma unroll
                for (int j = 0; j < 4; j++)
                    acc[i][j] = ffma2(ad, bp[j], acc[i][j]);
            }
        }
        if (t + 1 < nk) storeS((t + 1) & 1);
        __syncthreads();
    }
}

// ---------------- kernel 2: E = Q @ Wc^T + bc ----------------
__global__ __launch_bounds__(256, 2) void k_gemmE(const float* __restrict__ Q)
{
    const int rowBase = blockIdx.y * TILE, colBase = blockIdx.x * TILE;
    unsigned long long acc[8][4];
    gemm_core<DIM>(Q, g_Wc, rowBase, colBase, DIM, DIM, acc);

    const int tid = threadIdx.x, tx = tid & 15, ty = tid >> 4;
    const int ri0 = ty * 8, c0 = tx * 4;
    float4 bias0 = *(const float4*)&g_bc[colBase + c0];
    float4 bias1 = *(const float4*)&g_bc[colBase + 64 + c0];
    #pragma unroll
    for (int i = 0; i < 8; i++) {
        float2 p0 = unpk(acc[i][0]), p1 = unpk(acc[i][1]);
        float2 p2 = unpk(acc[i][2]), p3 = unpk(acc[i][3]);
        size_t rbase = (size_t)(rowBase + ri0 + i) * DIM;
        *(float4*)(g_E + rbase + colBase + c0) =
            make_float4(p0.x + bias0.x, p0.y + bias0.y, p1.x + bias0.z, p1.y + bias0.w);
        *(float4*)(g_E + rbase + colBase + 64 + c0) =
            make_float4(p2.x + bias1.x, p2.y + bias1.y, p3.x + bias1.z, p3.y + bias1.w);
    }
}

// ---------------- kernel 3: L2-normalize rows of E ----------------
__global__ void k_norm()
{
    const int row = blockIdx.x, tid = threadIdx.x;  // 128 threads
    float4* e = (float4*)(g_E + (size_t)row * DIM);
    float4 v = e[tid];
    float ss = v.x*v.x + v.y*v.y + v.z*v.z + v.w*v.w;
    #pragma unroll
    for (int o = 16; o > 0; o >>= 1) ss += __shfl_xor_sync(0xffffffffu, ss, o);
    __shared__ float sred[4];
    if ((tid & 31) == 0) sred[tid >> 5] = ss;
    __syncthreads();
    float tot = sred[0] + sred[1] + sred[2] + sred[3];
    float s = 1.0f / fmaxf(sqrtf(tot), 1e-12f);
    v.x *= s; v.y *= s; v.z *= s; v.w *= s;
    e[tid] = v;
}

// ---------------- kernel 4: symmetric GEMM C = E E^T (upper tiles + mirror) ----------------
__global__ __launch_bounds__(256, 2) void k_symgemm()
{
    int t = blockIdx.x, bi = 0;
    while (t >= NTILE - bi) { t -= NTILE - bi; bi++; }
    const int bj = bi + t;
    const int rowBase = bi * TILE, colBase = bj * TILE;

    unsigned long long acc[8][4];
    gemm_core<DIM>(g_E, g_E, rowBase, colBase, DIM, DIM, acc);

    const int tid = threadIdx.x, tx = tid & 15, ty = tid >> 4;
    const int ri0 = ty * 8, c0 = tx * 4;
    #pragma unroll
    for (int i = 0; i < 8; i++) {
        float2 p0 = unpk(acc[i][0]), p1 = unpk(acc[i][1]);
        float2 p2 = unpk(acc[i][2]), p3 = unpk(acc[i][3]);
        size_t rbase = (size_t)(rowBase + ri0 + i) * NROW;
        *(float4*)(g_C + rbase + colBase + c0)      = make_float4(p0.x, p0.y, p1.x, p1.y);
        *(float4*)(g_C + rbase + colBase + 64 + c0) = make_float4(p2.x, p2.y, p3.x, p3.y);
    }
    if (bi != bj) {  // mirror tile: per-column stores hit full aligned 32B sectors
        #pragma unroll
        for (int x = 0; x < 8; x++) {
            int gc = colBase + ((x < 4) ? (c0 + x) : (64 + c0 + x - 4));
            float v[8];
            #pragma unroll
            for (int i = 0; i < 8; i++) {
                float2 p = unpk(acc[i][x >> 1]);
                v[i] = (x & 1) ? p.y : p.x;
            }
            size_t base = (size_t)gc * NROW + rowBase + ri0;
            *(float4*)(g_C + base)     = make_float4(v[0], v[1], v[2], v[3]);
            *(float4*)(g_C + base + 4) = make_float4(v[4], v[5], v[6], v[7]);
        }
    }
}

// ---------------- kernel 5: zero the output ----------------
__global__ void k_zero(float4* __restrict__ out)
{
    const size_t n4 = (size_t)NROW * NROW / 4;
    const size_t stride = (size_t)gridDim.x * blockDim.x;
    for (size_t i = (size_t)blockIdx.x * blockDim.x + threadIdx.x; i < n4; i += stride)
        out[i] = make_float4(0.f, 0.f, 0.f, 0.f);
}

// ---------------- kernel 6: per-row exact top-49 (radix select) + scatter ----------------
__global__ __launch_bounds__(256) void k_topk(float* __restrict__ out)
{
    __shared__ unsigned int sk[NROW];        // 32 KB: encoded row
    __shared__ unsigned int hist[256];
    __shared__ unsigned int s_pval;
    __shared__ int s_krem;
    __shared__ int s_nsel;

    const int row = blockIdx.x, tid = threadIdx.x;
    const float* crow = g_C + (size_t)row * NROW;

    for (int v = tid; v < NROW / 4; v += 256) {
        float4 f = *(const float4*)(crow + v * 4);
        int c = v * 4;
        sk[c + 0] = enc_key(f.x); sk[c + 1] = enc_key(f.y);
        sk[c + 2] = enc_key(f.z); sk[c + 3] = enc_key(f.w);
    }
    __syncthreads();
    if (tid == 0) { sk[row] = 0u; s_pval = 0u; s_krem = KSEL; s_nsel = 0; }
    __syncthreads();

    // 4-level 8-bit radix select: find the 49th-largest key exactly.
    #pragma unroll
    for (int lvl = 0; lvl < 4; lvl++) {
        const int sh = 24 - 8 * lvl;
        hist[tid] = 0u;
        __syncthreads();
        const unsigned int pv = s_pval;
        const unsigned int pm = (lvl == 0) ? 0u : (0xFFFFFFFFu << (32 - 8 * lvl));
        for (int c = tid; c < NROW; c += 256) {
            unsigned int k = sk[c];
            if ((k & pm) == pv) atomicAdd(&hist[(k >> sh) & 255], 1u);
        }
        __syncthreads();
        if (tid == 0) {
            int kr = s_krem;
            int b = 255;
            for (;; b--) {
                int cnt = (int)hist[b];
                if (kr <= cnt || b == 0) break;
                kr -= cnt;
            }
            s_krem = kr;
            s_pval = pv | ((unsigned int)b << sh);
        }
        __syncthreads();
    }

    const unsigned int Kth = s_pval;
    // pass 1: all strictly greater than the threshold key
    for (int c = tid; c < NROW; c += 256) {
        unsigned int k = sk[c];
        if (k > Kth) {
            atomicAdd(&s_nsel, 1);
            float val = dec_key(k);
            out[(size_t)row * NROW + c] = val;
            out[(size_t)c * NROW + row] = val;
        }
    }
    __syncthreads();
    // pass 2: fill remaining slots with keys equal to threshold
    const float kval = dec_key(Kth);
    for (int c = tid; c < NROW; c += 256) {
        if (sk[c] == Kth) {
            int p = atomicAdd(&s_nsel, 1);
            if (p < KSEL) {
                out[(size_t)row * NROW + c] = kval;
                out[(size_t)c * NROW + row] = kval;
            }
        }
    }
    if (tid == 0) out[(size_t)row * NROW + row] = 1.0f;
}

// ---------------- launcher ----------------
extern "C" void kernel_launch(void* const* d_in, const int* in_sizes, int n_in,
                              void* d_out, int out_size)
{
    (void)in_sizes; (void)n_in; (void)out_size;
    const float* Q  = (const float*)d_in[0];
    const float* sw = (const float*)d_in[1];

    k_combine<<<(DIM * DIM + 255) / 256, 256>>>(sw,
        (const float*)d_in[2], (const float*)d_in[4],
        (const float*)d_in[6], (const float*)d_in[8],
        (const float*)d_in[3], (const float*)d_in[5],
        (const float*)d_in[7], (const float*)d_in[9]);

    dim3 ge(DIM / TILE, NROW / TILE);          // (4, 64)
    k_gemmE<<<ge, 256>>>(Q);

    k_norm<<<NROW, 128>>>();

    k_symgemm<<<NTILE * (NTILE + 1) / 2, 256>>>();   // 2080 upper-tri tiles

    k_zero<<<4096, 256>>>((float4*)d_out);

    k_topk<<<NROW, 256>>>((float*)d_out);
}